// round 1
// baseline (speedup 1.0000x reference)
#include <cuda_runtime.h>
#include <math.h>

#define T_TOK 4096
#define NH 1024          // hidden
#define NI 512           // intermediate
#define NE 16            // real experts
#define NSLOT 32         // real + zero slots
#define TOPK 4
#define MAXP 4096        // max pairs per expert (<= T)

// ---- static device scratch (no runtime allocation allowed) ----
__device__ int   g_cnt[NE];                       // pairs per expert
__device__ int   g_tok[NE * MAXP];                // token index per pair slot
__device__ float g_wt [NE * MAXP];                // routing weight per pair slot
__device__ int   g_tk_n[T_TOK];                   // real experts chosen per token
__device__ int   g_tk_pair[T_TOK * TOPK];         // pair indices per token (topk order)
__device__ float g_act [(size_t)NE * MAXP * NI];  // SwiGLU activations   (128 MB)
__device__ float g_pout[(size_t)NE * MAXP * NH];  // per-pair down output (256 MB)

// ---------------------------------------------------------------------------
__global__ void reset_kernel() {
    int i = threadIdx.x;
    if (i < NE) g_cnt[i] = 0;
}

// ---------------------------------------------------------------------------
// Router: one block (256 threads) per token.
// logits[32] = x . W_r^T ; softmax ; top-4 on (score+bias) ; weights from raw
// scores. Real experts appended to per-expert lists; zero experts accumulate
// zero_w. Also initializes out = zero_w * x.
__global__ void router_kernel(const float* __restrict__ x,
                              const float* __restrict__ rw,
                              const float* __restrict__ bias,
                              float* __restrict__ out) {
    int t = blockIdx.x;
    __shared__ float sc[NSLOT];
    __shared__ float s_zero;
    int tid  = threadIdx.x;           // 256
    int slot = tid >> 3;              // 32 slots, 8 threads each
    int sub  = tid & 7;
    const float* xr = x  + (size_t)t * NH;
    const float* wr = rw + (size_t)slot * NH;

    float acc = 0.f;
    for (int h = sub * 4; h < NH; h += 32) {
        float4 xv = *reinterpret_cast<const float4*>(xr + h);
        float4 wv = *reinterpret_cast<const float4*>(wr + h);
        acc += xv.x * wv.x + xv.y * wv.y + xv.z * wv.z + xv.w * wv.w;
    }
    acc += __shfl_down_sync(0xffffffffu, acc, 4, 8);
    acc += __shfl_down_sync(0xffffffffu, acc, 2, 8);
    acc += __shfl_down_sync(0xffffffffu, acc, 1, 8);
    if (sub == 0) sc[slot] = acc;
    __syncthreads();

    if (tid == 0) {
        // softmax (fp32, matches reference)
        float mx = -1e30f;
        for (int i = 0; i < NSLOT; i++) mx = fmaxf(mx, sc[i]);
        float e[NSLOT], sum = 0.f;
        for (int i = 0; i < NSLOT; i++) { e[i] = expf(sc[i] - mx); sum += e[i]; }
        float inv = 1.f / sum;
        float sb[NSLOT];
        for (int i = 0; i < NSLOT; i++) {
            sc[i] = e[i] * inv;            // raw score (weight source)
            sb[i] = sc[i] + bias[i];       // selection score
        }
        float zero_w = 0.f;
        int tkn = 0;
        for (int kk = 0; kk < TOPK; kk++) {
            int bi = 0; float bv = -1e30f;
            for (int i = 0; i < NSLOT; i++)
                if (sb[i] > bv) { bv = sb[i]; bi = i; }
            sb[bi] = -1e30f;
            float w = sc[bi];
            if (bi < NE) {
                int s2 = atomicAdd(&g_cnt[bi], 1);
                g_tok[bi * MAXP + s2] = t;
                g_wt [bi * MAXP + s2] = w;
                g_tk_pair[t * TOPK + tkn] = bi * MAXP + s2;
                tkn++;
            } else {
                zero_w += w;
            }
        }
        g_tk_n[t] = tkn;
        s_zero = zero_w;
    }
    __syncthreads();

    float zw = s_zero;
    for (int h = tid; h < NH; h += 256)
        out[(size_t)t * NH + h] = zw * xr[h];
}

// ---------------------------------------------------------------------------
// GEMM1: act[pair, i] = silu(x . w_gate) * (x . w_up)   (per expert group)
// Tiled 64x64, KT=16, 256 threads, 4x4 per thread, two B matrices fused.
#define TM 64
#define TN 64
#define KT 16

__global__ void gemm1_kernel(const float* __restrict__ x,
                             const float* __restrict__ wg,
                             const float* __restrict__ wu) {
    int e    = blockIdx.z;
    int cnt  = g_cnt[e];
    int row0 = blockIdx.y * TM;
    if (row0 >= cnt) return;
    int col0 = blockIdx.x * TN;

    __shared__ float As[KT][TM + 4];
    __shared__ float Bg[KT][TN];
    __shared__ float Bu[KT][TN];

    int tid = threadIdx.x;            // 256
    int am  = tid >> 2;               // 0..63 (row within tile)
    int ak  = (tid & 3) * 4;          // 0,4,8,12
    int bk  = tid >> 4;               // 0..15
    int bn  = (tid & 15) * 4;         // 0..60
    int tx  = tid & 15, ty = tid >> 4;

    int arow  = row0 + am;
    int tokIdx = (arow < cnt) ? g_tok[e * MAXP + arow] : -1;
    const float* wgB = wg + (size_t)e * NH * NI;
    const float* wuB = wu + (size_t)e * NH * NI;

    float accg[4][4] = {}, accu[4][4] = {};

    for (int k0 = 0; k0 < NH; k0 += KT) {
        float4 av = make_float4(0.f, 0.f, 0.f, 0.f);
        if (tokIdx >= 0)
            av = *reinterpret_cast<const float4*>(x + (size_t)tokIdx * NH + k0 + ak);
        As[ak + 0][am] = av.x; As[ak + 1][am] = av.y;
        As[ak + 2][am] = av.z; As[ak + 3][am] = av.w;

        *reinterpret_cast<float4*>(&Bg[bk][bn]) =
            *reinterpret_cast<const float4*>(wgB + (size_t)(k0 + bk) * NI + col0 + bn);
        *reinterpret_cast<float4*>(&Bu[bk][bn]) =
            *reinterpret_cast<const float4*>(wuB + (size_t)(k0 + bk) * NI + col0 + bn);
        __syncthreads();

#pragma unroll
        for (int k = 0; k < KT; k++) {
            float a[4];
#pragma unroll
            for (int i = 0; i < 4; i++) a[i] = As[k][ty * 4 + i];
            float4 bg4 = *reinterpret_cast<const float4*>(&Bg[k][tx * 4]);
            float4 bu4 = *reinterpret_cast<const float4*>(&Bu[k][tx * 4]);
            float bgv[4] = {bg4.x, bg4.y, bg4.z, bg4.w};
            float buv[4] = {bu4.x, bu4.y, bu4.z, bu4.w};
#pragma unroll
            for (int i = 0; i < 4; i++)
#pragma unroll
                for (int j = 0; j < 4; j++) {
                    accg[i][j] += a[i] * bgv[j];
                    accu[i][j] += a[i] * buv[j];
                }
        }
        __syncthreads();
    }

    size_t base = (size_t)e * MAXP;
#pragma unroll
    for (int i = 0; i < 4; i++) {
        int r = row0 + ty * 4 + i;
        if (r < cnt) {
#pragma unroll
            for (int j = 0; j < 4; j++) {
                float g = accg[i][j], u = accu[i][j];
                float s = g / (1.f + expf(-g));
                g_act[(base + r) * NI + col0 + tx * 4 + j] = s * u;
            }
        }
    }
}

// ---------------------------------------------------------------------------
// GEMM2: pout[pair, h] = wt[pair] * (act[pair,:] . w_down[e][:,h])
__global__ void gemm2_kernel(const float* __restrict__ wd) {
    int e    = blockIdx.z;
    int cnt  = g_cnt[e];
    int row0 = blockIdx.y * TM;
    if (row0 >= cnt) return;
    int col0 = blockIdx.x * TN;

    __shared__ float As[KT][TM + 4];
    __shared__ float Bs[KT][TN];

    int tid = threadIdx.x;
    int am  = tid >> 2;
    int ak  = (tid & 3) * 4;
    int bk  = tid >> 4;
    int bn  = (tid & 15) * 4;
    int tx  = tid & 15, ty = tid >> 4;

    int arow = row0 + am;
    bool avalid = (arow < cnt);
    size_t base = (size_t)e * MAXP;
    const float* wdB = wd + (size_t)e * NI * NH;

    float acc[4][4] = {};

    for (int k0 = 0; k0 < NI; k0 += KT) {
        float4 av = make_float4(0.f, 0.f, 0.f, 0.f);
        if (avalid)
            av = *reinterpret_cast<const float4*>(&g_act[(base + arow) * NI + k0 + ak]);
        As[ak + 0][am] = av.x; As[ak + 1][am] = av.y;
        As[ak + 2][am] = av.z; As[ak + 3][am] = av.w;

        *reinterpret_cast<float4*>(&Bs[bk][bn]) =
            *reinterpret_cast<const float4*>(wdB + (size_t)(k0 + bk) * NH + col0 + bn);
        __syncthreads();

#pragma unroll
        for (int k = 0; k < KT; k++) {
            float a[4];
#pragma unroll
            for (int i = 0; i < 4; i++) a[i] = As[k][ty * 4 + i];
            float4 b4 = *reinterpret_cast<const float4*>(&Bs[k][tx * 4]);
            float bv[4] = {b4.x, b4.y, b4.z, b4.w};
#pragma unroll
            for (int i = 0; i < 4; i++)
#pragma unroll
                for (int j = 0; j < 4; j++)
                    acc[i][j] += a[i] * bv[j];
        }
        __syncthreads();
    }

#pragma unroll
    for (int i = 0; i < 4; i++) {
        int r = row0 + ty * 4 + i;
        if (r < cnt) {
            float w = g_wt[e * MAXP + r];
#pragma unroll
            for (int j = 0; j < 4; j++)
                g_pout[(base + r) * NH + col0 + tx * 4 + j] = acc[i][j] * w;
        }
    }
}

// ---------------------------------------------------------------------------
// Combine: out[t] += sum over this token's pairs of pout  (no float atomics,
// summation order fixed by top-k order -> deterministic)
__global__ void combine_kernel(float* __restrict__ out) {
    int t  = blockIdx.x;
    int np = g_tk_n[t];
    int p[TOPK];
    for (int j = 0; j < np; j++) p[j] = g_tk_pair[t * TOPK + j];
    for (int h = threadIdx.x; h < NH; h += 256) {
        float s = 0.f;
        for (int j = 0; j < np; j++)
            s += g_pout[(size_t)p[j] * NH + h];
        out[(size_t)t * NH + h] += s;
    }
}

// ---------------------------------------------------------------------------
extern "C" void kernel_launch(void* const* d_in, const int* in_sizes, int n_in,
                              void* d_out, int out_size) {
    (void)in_sizes; (void)n_in; (void)out_size;
    const float* x    = (const float*)d_in[0];
    const float* rw   = (const float*)d_in[1];
    const float* bias = (const float*)d_in[2];
    const float* wg   = (const float*)d_in[3];
    const float* wu   = (const float*)d_in[4];
    const float* wd   = (const float*)d_in[5];
    float* out = (float*)d_out;

    reset_kernel<<<1, 32>>>();
    router_kernel<<<T_TOK, 256>>>(x, rw, bias, out);

    dim3 g1(NI / TN, T_TOK / TM, NE);
    gemm1_kernel<<<g1, 256>>>(x, wg, wu);

    dim3 g2(NH / TN, T_TOK / TM, NE);
    gemm2_kernel<<<g2, 256>>>(wd);

    combine_kernel<<<T_TOK, 256>>>(out);
}